// round 8
// baseline (speedup 1.0000x reference)
#include <cuda_runtime.h>
#include <cuda_bf16.h>
#include <cstdint>

#define B_   256
#define N_   144
#define M_   (B_ * N_)            // 36864 rows
#define SCALE_ 0.125f             // 64^-0.5

// ---------------- scratch (device globals: allocation-free rule) -------------
__device__ float g_kv [(size_t)M_ * 1024];
__device__ float g_q  [(size_t)M_ * 512];
__device__ float g_att[(size_t)M_ * 512];

// bf16 hi|lo split operands: [rows, 1024] = [hi(512) | lo(512)]
__device__ __nv_bfloat16 g_xte [(size_t)M_ * 1024];   // x + is_end*topo
__device__ __nv_bfloat16 g_xe  [(size_t)M_ * 1024];   // x
__device__ __nv_bfloat16 g_ae  [(size_t)M_ * 1024];   // attention out
__device__ __nv_bfloat16 g_wkve[(size_t)1024 * 1024];
__device__ __nv_bfloat16 g_wqe [(size_t)512 * 1024];
__device__ __nv_bfloat16 g_wpe [(size_t)512 * 1024];

// ---------------- helpers ------------------------------------------------------
__device__ __forceinline__ uint32_t smem_u32(const void* p) {
    uint32_t a;
    asm("{ .reg .u64 t; cvta.to.shared.u64 t, %1; cvt.u32.u64 %0, t; }" : "=r"(a) : "l"(p));
    return a;
}
__device__ __forceinline__ void ldsm_x4(uint32_t& r0, uint32_t& r1, uint32_t& r2,
                                        uint32_t& r3, uint32_t addr) {
    asm volatile("ldmatrix.sync.aligned.m8n8.x4.shared.b16 {%0,%1,%2,%3}, [%4];"
                 : "=r"(r0), "=r"(r1), "=r"(r2), "=r"(r3) : "r"(addr));
}
__device__ __forceinline__ void mma_bf16(float* c, uint32_t a0, uint32_t a1,
                                         uint32_t a2, uint32_t a3,
                                         uint32_t b0, uint32_t b1) {
    asm volatile(
        "mma.sync.aligned.m16n8k16.row.col.f32.bf16.bf16.f32 "
        "{%0,%1,%2,%3}, {%4,%5,%6,%7}, {%8,%9}, {%0,%1,%2,%3};"
        : "+f"(c[0]), "+f"(c[1]), "+f"(c[2]), "+f"(c[3])
        : "r"(a0), "r"(a1), "r"(a2), "r"(a3), "r"(b0), "r"(b1));
}
__device__ __forceinline__ void split1(float v, __nv_bfloat16& h, __nv_bfloat16& l) {
    h = __float2bfloat16_rn(v);
    l = __float2bfloat16_rn(v - __bfloat162float(h));
}
__device__ __forceinline__ void cp16(uint32_t dst, const void* src) {
    asm volatile("cp.async.cg.shared.global [%0], [%1], 16;" :: "r"(dst), "l"(src));
}
// packed f32x2
__device__ __forceinline__ unsigned long long pack2(float lo, float hi) {
    unsigned long long r;
    asm("mov.b64 %0, {%1, %2};" : "=l"(r) : "f"(lo), "f"(hi));
    return r;
}
__device__ __forceinline__ void fma2(unsigned long long& d, unsigned long long a, unsigned long long b) {
    asm("fma.rn.f32x2 %0, %1, %2, %0;" : "+l"(d) : "l"(a), "l"(b));
}
__device__ __forceinline__ float2 unpack2(unsigned long long v) {
    float2 r;
    asm("mov.b64 {%0, %1}, %2;" : "=f"(r.x), "=f"(r.y) : "l"(v));
    return r;
}

// ---------------- fp32 -> bf16 hi/lo split (single stream) --------------------
__global__ __launch_bounds__(256)
void split_bf16_kernel(const float4* __restrict__ in, __nv_bfloat16* __restrict__ out,
                       long total4)
{
    long i = (long)blockIdx.x * blockDim.x + threadIdx.x;
    if (i >= total4) return;
    float4 a = in[i];
    long idx = i * 4;
    long row = idx >> 9;
    int  col = (int)(idx & 511);
    float v[4] = { a.x, a.y, a.z, a.w };
    __nv_bfloat16 h[4], l[4];
#pragma unroll
    for (int j = 0; j < 4; j++) split1(v[j], h[j], l[j]);
    __nv_bfloat16* base = out + row * 1024 + col;
    *(uint2*)(base)       = *(uint2*)h;
    *(uint2*)(base + 512) = *(uint2*)l;
}

// dual: oxe = split(x), oxte = split(x + f*topo)
__global__ __launch_bounds__(256)
void split_dual_kernel(const float4* __restrict__ x, const float4* __restrict__ topo,
                       const int* __restrict__ flag,
                       __nv_bfloat16* __restrict__ oxe, __nv_bfloat16* __restrict__ oxte,
                       long total4)
{
    long i = (long)blockIdx.x * blockDim.x + threadIdx.x;
    if (i >= total4) return;
    float4 a = x[i];
    float4 tp = topo[i];
    float f = (*flag != 0) ? 1.f : 0.f;
    long idx = i * 4;
    long row = idx >> 9;
    int  col = (int)(idx & 511);
    float v1[4] = { a.x, a.y, a.z, a.w };
    float v2[4] = { a.x + f * tp.x, a.y + f * tp.y, a.z + f * tp.z, a.w + f * tp.w };
    __nv_bfloat16 h[4], l[4];
#pragma unroll
    for (int j = 0; j < 4; j++) split1(v1[j], h[j], l[j]);
    __nv_bfloat16* b1 = oxe + row * 1024 + col;
    *(uint2*)(b1)       = *(uint2*)h;
    *(uint2*)(b1 + 512) = *(uint2*)l;
#pragma unroll
    for (int j = 0; j < 4; j++) split1(v2[j], h[j], l[j]);
    __nv_bfloat16* b2 = oxte + row * 1024 + col;
    *(uint2*)(b2)       = *(uint2*)h;
    *(uint2*)(b2 + 512) = *(uint2*)l;
}

// ---------------- mma.sync bf16 GEMM: unique-tile staging ----------------------
// 16 K-chunks of 32. Per chunk load Ahi/Alo/Bhi/Blo [128x32] ONCE via cp.async,
// run 3 passes (AhiBhi, AloBhi, AhiBlo) from smem. Pitch 80B: row stride =
// 20 banks -> 8 ldmatrix rows partition all 32 banks (starts {0,20,8,28,16,4,24,12}).
#define GPITCH  80
#define GTILE   (128 * GPITCH)            // 10240 B
#define GBUF    (4 * GTILE)               // Ahi,Alo,Bhi,Blo = 40960 B
#define GEMM_SMEM (2 * GBUF)              // 81920 B double-buffered

__global__ __launch_bounds__(256, 2)
void gemm_mma_kernel(const __nv_bfloat16* __restrict__ A,
                     const __nv_bfloat16* __restrict__ Bw,
                     const float* __restrict__ bias,
                     float* __restrict__ C, int Nc)
{
    extern __shared__ __align__(128) char smem[];
    const uint32_t sbase = smem_u32(smem);

    const int t    = threadIdx.x;
    const int lane = t & 31;
    const int w    = t >> 5;
    const int wm   = w >> 2;
    const int wn   = w & 3;
    const int row0 = blockIdx.y * 128;
    const int col0 = blockIdx.x * 128;

    // ldmatrix lane addresses (tile-relative)
    const uint32_t aOff = (uint32_t)(wm * 64 + (lane & 15)) * GPITCH + (lane >> 4) * 16;
    const uint32_t bOff = (uint32_t)(wn * 32 + (lane & 7) + ((lane >> 4) & 1) * 8) * GPITCH
                        + ((lane >> 3) & 1) * 16;

    float acc[4][4][4];
#pragma unroll
    for (int mi = 0; mi < 4; mi++)
#pragma unroll
        for (int nj = 0; nj < 4; nj++)
#pragma unroll
            for (int e = 0; e < 4; e++) acc[mi][nj][e] = 0.f;

    // staging map: thread t -> row t>>1 (0..127), 2 16B chunks ((t&1)*2 + {0,1})
    const int rowT = t >> 1;
    const int ch0  = (t & 1) * 2;
    const __nv_bfloat16* Ag = A  + (size_t)(row0 + rowT) * 1024 + ch0 * 8;
    const __nv_bfloat16* Bg = Bw + (size_t)(col0 + rowT) * 1024 + ch0 * 8;
    const uint32_t stBase = sbase + (uint32_t)rowT * GPITCH + ch0 * 16;

    auto stage = [&](int c, uint32_t bufOff) {
        const int k0 = c * 32;
#pragma unroll
        for (int u = 0; u < 2; u++) {
            cp16(stBase + bufOff + 0 * GTILE + u * 16, Ag + k0 + u * 8);          // A-hi
            cp16(stBase + bufOff + 1 * GTILE + u * 16, Ag + 512 + k0 + u * 8);    // A-lo
            cp16(stBase + bufOff + 2 * GTILE + u * 16, Bg + k0 + u * 8);          // B-hi
            cp16(stBase + bufOff + 3 * GTILE + u * 16, Bg + 512 + k0 + u * 8);    // B-lo
        }
        asm volatile("cp.async.commit_group;" ::: "memory");
    };

    stage(0, 0);
    for (int c = 0; c < 16; c++) {
        asm volatile("cp.async.wait_group 0;" ::: "memory");
        __syncthreads();
        if (c < 15) stage(c + 1, (uint32_t)((c + 1) & 1) * GBUF);
        const uint32_t bufOff = (uint32_t)(c & 1) * GBUF;

        // 3 passes: (Ahi,Bhi), (Alo,Bhi), (Ahi,Blo)
#pragma unroll
        for (int p = 0; p < 3; p++) {
            const uint32_t aT = sbase + bufOff + ((p == 1) ? GTILE : 0) + aOff;
            const uint32_t bT = sbase + bufOff + 2 * GTILE + ((p == 2) ? GTILE : 0) + bOff;
#pragma unroll
            for (int ks = 0; ks < 2; ks++) {
                uint32_t ar[4][4], br[2][4];
#pragma unroll
                for (int mi = 0; mi < 4; mi++)
                    ldsm_x4(ar[mi][0], ar[mi][1], ar[mi][2], ar[mi][3],
                            aT + (uint32_t)mi * 16 * GPITCH + ks * 32);
#pragma unroll
                for (int pj = 0; pj < 2; pj++)
                    ldsm_x4(br[pj][0], br[pj][1], br[pj][2], br[pj][3],
                            bT + (uint32_t)pj * 16 * GPITCH + ks * 32);
#pragma unroll
                for (int mi = 0; mi < 4; mi++)
#pragma unroll
                    for (int nj = 0; nj < 4; nj++) {
                        const int pj = nj >> 1, hb = (nj & 1) * 2;
                        mma_bf16(acc[mi][nj], ar[mi][0], ar[mi][1], ar[mi][2], ar[mi][3],
                                 br[pj][hb], br[pj][hb + 1]);
                    }
            }
        }
    }

    const int rbase = row0 + wm * 64 + (lane >> 2);
    const int cbase = col0 + wn * 32 + (lane & 3) * 2;
#pragma unroll
    for (int mi = 0; mi < 4; mi++) {
#pragma unroll
        for (int nj = 0; nj < 4; nj++) {
            const int r  = rbase + mi * 16;
            const int cc = cbase + nj * 8;
            float b0 = 0.f, b1 = 0.f;
            if (bias) { b0 = bias[cc]; b1 = bias[cc + 1]; }
            *(float2*)(C + (size_t)r * Nc + cc) =
                make_float2(acc[mi][nj][0] + b0, acc[mi][nj][1] + b1);
            *(float2*)(C + (size_t)(r + 8) * Nc + cc) =
                make_float2(acc[mi][nj][2] + b0, acc[mi][nj][3] + b1);
        }
    }
}

// ---------------- attention v3 (unchanged from round 6/7) ---------------------
#define AP   145
#define VP   68
#define QT_OFF 0
#define KT_OFF (64 * AP)
#define V_OFF  (2 * 64 * AP)
#define PT_OFF (2 * 64 * AP + 144 * VP)
#define ATTN_SMEM_FLOATS (2 * 64 * AP + 144 * VP + 144 * AP)
#define ATTN_SMEM_BYTES  (ATTN_SMEM_FLOATS * 4)

__global__ __launch_bounds__(256, 1)
void attn_kernel(const float* __restrict__ q, const float* __restrict__ kv,
                 float* __restrict__ o)
{
    extern __shared__ float sm[];
    float* Qt = sm + QT_OFF;
    float* Kt = sm + KT_OFF;
    float* Vs = sm + V_OFF;
    float* Pt = sm + PT_OFF;
    float* red = Pt;

    const int b = blockIdx.x >> 3;
    const int h = blockIdx.x & 7;
    const int t = threadIdx.x;
    const int ty = t >> 4;
    const int tx = t & 15;

    const float* qb = q  + (size_t)b * 144 * 512  + h * 64;
    const float* kb = kv + (size_t)b * 144 * 1024 + h * 64;
    const float* vb = kb + 512;

    for (int i = t; i < 144 * 64; i += 256) {
        int r = i >> 6, k = i & 63;
        Qt[k * AP + r] = qb[(size_t)r * 512 + k] * SCALE_;
        Kt[k * AP + r] = kb[(size_t)r * 1024 + k];
    }
    for (int i = t; i < 144 * 16; i += 256) {
        int n = i >> 4, cc = (i & 15) << 2;
        *(float4*)(Vs + n * VP + cc) = *(const float4*)(vb + (size_t)n * 1024 + cc);
    }
    __syncthreads();

    unsigned long long acc2[9][4];
    float acc8[9];
#pragma unroll
    for (int i = 0; i < 9; i++) {
#pragma unroll
        for (int jp = 0; jp < 4; jp++) acc2[i][jp] = 0ull;
        acc8[i] = 0.f;
    }

    const float* Qb = Qt + ty * 9;
    const float* Kb = Kt + tx * 9;
#pragma unroll 2
    for (int k = 0; k < 64; k++) {
        float qv[9], kvv[9];
#pragma unroll
        for (int i = 0; i < 9; i++) qv[i]  = Qb[k * AP + i];
#pragma unroll
        for (int j = 0; j < 9; j++) kvv[j] = Kb[k * AP + j];
        unsigned long long kp[4] = { pack2(kvv[0], kvv[1]), pack2(kvv[2], kvv[3]),
                                     pack2(kvv[4], kvv[5]), pack2(kvv[6], kvv[7]) };
#pragma unroll
        for (int i = 0; i < 9; i++) {
            unsigned long long qd = pack2(qv[i], qv[i]);
#pragma unroll
            for (int jp = 0; jp < 4; jp++) fma2(acc2[i][jp], qd, kp[jp]);
            acc8[i] += qv[i] * kvv[8];
        }
    }

    float s[9][9];
#pragma unroll
    for (int i = 0; i < 9; i++) {
#pragma unroll
        for (int jp = 0; jp < 4; jp++) {
            float2 u = unpack2(acc2[i][jp]);
            s[i][2 * jp]     = u.x;
            s[i][2 * jp + 1] = u.y;
        }
        s[i][8] = acc8[i];
    }

#pragma unroll
    for (int i = 0; i < 9; i++) {
        float m = s[i][0];
#pragma unroll
        for (int j = 1; j < 9; j++) m = fmaxf(m, s[i][j]);
        red[(ty * 9 + i) * 17 + tx] = m;
    }
    __syncthreads();
    float mrow[9];
#pragma unroll
    for (int i = 0; i < 9; i++) {
        const float* rr = red + (ty * 9 + i) * 17;
        float m = rr[0];
#pragma unroll
        for (int u = 1; u < 16; u++) m = fmaxf(m, rr[u]);
        mrow[i] = m;
    }
    __syncthreads();
#pragma unroll
    for (int i = 0; i < 9; i++) {
        float sum = 0.f;
#pragma unroll
        for (int j = 0; j < 9; j++) {
            float e = __expf(s[i][j] - mrow[i]);
            s[i][j] = e;
            sum += e;
        }
        red[(ty * 9 + i) * 17 + tx] = sum;
    }
    __syncthreads();
    float inv[9];
#pragma unroll
    for (int i = 0; i < 9; i++) {
        const float* rr = red + (ty * 9 + i) * 17;
        float sum = rr[0];
#pragma unroll
        for (int u = 1; u < 16; u++) sum += rr[u];
        inv[i] = 1.f / sum;
    }
    __syncthreads();

#pragma unroll
    for (int j = 0; j < 9; j++)
#pragma unroll
        for (int i = 0; i < 9; i++)
            Pt[(tx * 9 + j) * AP + (ty * 9 + i)] = s[i][j];
    __syncthreads();

    unsigned long long out2[9][2];
#pragma unroll
    for (int i = 0; i < 9; i++) { out2[i][0] = 0ull; out2[i][1] = 0ull; }

    const float* Pb = Pt + ty * 9;
#pragma unroll 2
    for (int j = 0; j < 144; j++) {
        float pv[9];
#pragma unroll
        for (int i = 0; i < 9; i++) pv[i] = Pb[j * AP + i];
        float4 vv = *(const float4*)(Vs + j * VP + tx * 4);
        unsigned long long v01 = pack2(vv.x, vv.y);
        unsigned long long v23 = pack2(vv.z, vv.w);
#pragma unroll
        for (int i = 0; i < 9; i++) {
            unsigned long long pd = pack2(pv[i], pv[i]);
            fma2(out2[i][0], pd, v01);
            fma2(out2[i][1], pd, v23);
        }
    }

    float* ob = o + (size_t)b * 144 * 512 + h * 64;
#pragma unroll
    for (int i = 0; i < 9; i++) {
        int r = ty * 9 + i;
        float2 o01 = unpack2(out2[i][0]);
        float2 o23 = unpack2(out2[i][1]);
        *(float4*)(ob + (size_t)r * 512 + tx * 4) =
            make_float4(o01.x * inv[i], o01.y * inv[i],
                        o23.x * inv[i], o23.y * inv[i]);
    }
}

// ---------------- launch -------------------------------------------------------
extern "C" void kernel_launch(void* const* d_in, const int* in_sizes, int n_in,
                              void* d_out, int out_size)
{
    const float* x      = (const float*)d_in[0];
    const float* topo   = (const float*)d_in[1];
    const float* kv_w   = (const float*)d_in[2];
    const float* q_w    = (const float*)d_in[3];
    const float* proj_w = (const float*)d_in[4];
    const float* proj_b = (const float*)d_in[5];
    const int*   is_end = (const int*)d_in[6];

    void *pkv, *pq, *patt, *pxte, *pxe, *pae, *pwkv, *pwq, *pwp;
    cudaGetSymbolAddress(&pkv,  g_kv);
    cudaGetSymbolAddress(&pq,   g_q);
    cudaGetSymbolAddress(&patt, g_att);
    cudaGetSymbolAddress(&pxte, g_xte);
    cudaGetSymbolAddress(&pxe,  g_xe);
    cudaGetSymbolAddress(&pae,  g_ae);
    cudaGetSymbolAddress(&pwkv, g_wkve);
    cudaGetSymbolAddress(&pwq,  g_wqe);
    cudaGetSymbolAddress(&pwp,  g_wpe);

    cudaFuncSetAttribute(attn_kernel, cudaFuncAttributeMaxDynamicSharedMemorySize,
                         ATTN_SMEM_BYTES);
    cudaFuncSetAttribute(gemm_mma_kernel, cudaFuncAttributeMaxDynamicSharedMemorySize,
                         GEMM_SMEM);

    const long act4 = (long)M_ * 512 / 4;
    const long wkv4 = 1024L * 512 / 4;
    const long w4   = 512L * 512 / 4;
    const int  TB   = 256;

    split_dual_kernel<<<(unsigned)((act4 + TB - 1) / TB), TB>>>(
        (const float4*)x, (const float4*)topo, is_end,
        (__nv_bfloat16*)pxe, (__nv_bfloat16*)pxte, act4);
    split_bf16_kernel<<<(unsigned)((wkv4 + TB - 1) / TB), TB>>>(
        (const float4*)kv_w, (__nv_bfloat16*)pwkv, wkv4);
    split_bf16_kernel<<<(unsigned)((w4 + TB - 1) / TB), TB>>>(
        (const float4*)q_w, (__nv_bfloat16*)pwq, w4);
    split_bf16_kernel<<<(unsigned)((w4 + TB - 1) / TB), TB>>>(
        (const float4*)proj_w, (__nv_bfloat16*)pwp, w4);

    gemm_mma_kernel<<<dim3(8, 288), 256, GEMM_SMEM>>>(
        (const __nv_bfloat16*)pxte, (const __nv_bfloat16*)pwkv, nullptr, (float*)pkv, 1024);
    gemm_mma_kernel<<<dim3(4, 288), 256, GEMM_SMEM>>>(
        (const __nv_bfloat16*)pxe, (const __nv_bfloat16*)pwq, nullptr, (float*)pq, 512);
    attn_kernel<<<B_ * 8, 256, ATTN_SMEM_BYTES>>>((float*)pq, (float*)pkv, (float*)patt);
    split_bf16_kernel<<<(unsigned)((act4 + TB - 1) / TB), TB>>>(
        (const float4*)patt, (__nv_bfloat16*)pae, act4);
    gemm_mma_kernel<<<dim3(4, 288), 256, GEMM_SMEM>>>(
        (const __nv_bfloat16*)pae, (const __nv_bfloat16*)pwp, proj_b, (float*)d_out, 512);
}